// round 1
// baseline (speedup 1.0000x reference)
#include <cuda_runtime.h>
#include <mma.h>

using namespace nvcuda;

// ---------------- problem constants ----------------
#define BATCH 1024
#define TSTEPS 256
#define DPART 64
#define ADIM 8
#define HDIM 256
#define HIDDIM 256
#define FDIM 65          // DP + 1 (weight channel)
#define KH 256           // h part of K
#define KTOT 321         // h(256) + particles(64) + weight(1)
#define KPAD 336         // padded to multiple of BK
#define NPACK 1024       // 256 hidden units * 4 packed cols (r, z, nf, hpn)

// GRU step GEMM tiling
#define BM 64
#define BN 128
#define BK 48

// ---------------- device scratch (static; no allocs allowed) ----------------
__device__ float g_Wp[KPAD * NPACK];       // packed tf32-rounded weights
__device__ float g_h[2][BATCH * HDIM];     // ping-pong GRU state (fp32)
__device__ float g_mlp1[2 * BATCH * HIDDIM];
__device__ float g_mlp2[2 * BATCH * HIDDIM];

// ---------------- weight packing ----------------
// col layout: hb in [0,8), within 128-col block: [r(32) | z(32) | nf(32) | hpn(32)]
// rows: k<256 -> Wh[k][gatecol]; 256<=k<321 -> Wi[k-256][gatecol]; hpn panel: Wh only.
__global__ void prep_weights(const float* __restrict__ Wi, const float* __restrict__ Wh) {
    int idx = blockIdx.x * blockDim.x + threadIdx.x;
    if (idx >= KPAD * NPACK) return;
    int k = idx / NPACK;
    int col = idx % NPACK;
    int hb = col >> 7;
    int rem = col & 127;
    int panel = rem >> 5;
    int u = rem & 31;
    int j = hb * 32 + u;                 // hidden unit index
    float w = 0.0f;
    if (panel < 3) {
        int g = j + panel * 256;         // gate column in [0,768)
        if (k < KH)            w = Wh[k * 768 + g];
        else if (k < KTOT)     w = Wi[(k - KH) * 768 + g];
    } else {                             // hpn: h @ Wh_n only
        if (k < KH)            w = Wh[k * 768 + (j + 512)];
    }
    g_Wp[idx] = wmma::__float_to_tf32(w);
}

__global__ void zero_h() {
    int i = blockIdx.x * blockDim.x + threadIdx.x;
    if (i < BATCH * HDIM) g_h[0][i] = 0.0f;
}

// ---------------- GRU step: C[1024, NPACK] = A[1024, KPAD] @ g_Wp, fused gates ----------------
__global__ void __launch_bounds__(256) gru_step(
    const float* __restrict__ particles,   // [B, T, DP]
    const float* __restrict__ pweights,    // [B, T]
    const float* __restrict__ bi,          // [768]
    const float* __restrict__ bhn,         // [256]
    int t, int parity)
{
    const float* __restrict__ h_in = g_h[parity];
    float* __restrict__ h_out      = g_h[parity ^ 1];

    __shared__ float smem[BM * BK + BK * BN];   // 9216 floats = 36 KB
    float* As = smem;                            // [BM][BK]
    float* Bs = smem + BM * BK;                  // [BK][BN]
    float* Cs = smem;                            // reused after K loop: [BM][BN]

    int tid  = threadIdx.x;
    int warp = tid >> 5;
    int wr   = warp & 3;      // warp row -> rows wr*16
    int wc   = warp >> 1;     // placeholder (recomputed below)
    wc = warp >> 2;           // warp col in {0,1} -> cols wc*64
    int row0 = blockIdx.x * BM;
    int col0 = blockIdx.y * BN;
    int hb   = blockIdx.y;

    wmma::fragment<wmma::accumulator, 16, 16, 8, float> acc[4];
#pragma unroll
    for (int i = 0; i < 4; i++) wmma::fill_fragment(acc[i], 0.0f);

    for (int k0 = 0; k0 < KPAD; k0 += BK) {
        // ---- load A tile (construct [h | particles_t | weight_t | 0-pad]) ----
#pragma unroll
        for (int i = tid; i < BM * BK; i += 256) {
            int r = i / BK;
            int k = k0 + (i % BK);
            int gb = row0 + r;
            float v;
            if (k < KH)                 v = h_in[gb * HDIM + k];
            else if (k < KH + DPART)    v = particles[(gb * TSTEPS + t) * DPART + (k - KH)];
            else if (k == KH + DPART)   v = pweights[gb * TSTEPS + t];
            else                        v = 0.0f;
            As[i] = wmma::__float_to_tf32(v);
        }
        // ---- load B tile (already tf32-rounded) ----
#pragma unroll
        for (int i = tid; i < (BK * BN) / 4; i += 256) {
            int r  = i / (BN / 4);
            int c4 = i % (BN / 4);
            reinterpret_cast<float4*>(Bs)[r * (BN / 4) + c4] =
                reinterpret_cast<const float4*>(g_Wp + (size_t)(k0 + r) * NPACK + col0)[c4];
        }
        __syncthreads();

#pragma unroll
        for (int kk = 0; kk < BK; kk += 8) {
            wmma::fragment<wmma::matrix_a, 16, 16, 8, wmma::precision::tf32, wmma::row_major> af;
            wmma::load_matrix_sync(af, As + (wr * 16) * BK + kk, BK);
#pragma unroll
            for (int ct = 0; ct < 4; ct++) {
                wmma::fragment<wmma::matrix_b, 16, 16, 8, wmma::precision::tf32, wmma::row_major> bf;
                wmma::load_matrix_sync(bf, Bs + kk * BN + wc * 64 + ct * 16, BN);
                wmma::mma_sync(acc[ct], af, bf, acc[ct]);
            }
        }
        __syncthreads();
    }

    // ---- stage C tile to SMEM for the gate epilogue ----
#pragma unroll
    for (int ct = 0; ct < 4; ct++)
        wmma::store_matrix_sync(Cs + (wr * 16) * BN + wc * 64 + ct * 16, acc[ct], BN, wmma::mem_row_major);
    __syncthreads();

    // ---- fused GRU gate epilogue: 64 rows x 32 hidden units ----
    for (int i = tid; i < BM * 32; i += 256) {
        int r = i >> 5;
        int u = i & 31;
        int gb = row0 + r;
        int j  = hb * 32 + u;
        float sr  = Cs[r * BN + u]        + bi[j];
        float sz  = Cs[r * BN + 32 + u]   + bi[256 + j];
        float snf = Cs[r * BN + 64 + u]   + bi[512 + j];
        float hpn = Cs[r * BN + 96 + u];
        float rg = 1.0f / (1.0f + expf(-sr));
        float zg = 1.0f / (1.0f + expf(-sz));
        float xn = snf - hpn;                       // x_n (+ bi_n)
        float ng = tanhf(xn + rg * (hpn + bhn[j]));
        float ho = h_in[gb * HDIM + j];
        h_out[gb * HDIM + j] = (1.0f - zg) * ng + zg * ho;
    }
}

// ---------------- MLP layers (fp32 SIMT tiled GEMM, 64x64x16, 4x4 microtile) ----------------
// mode 0: A = [h_final | action | t/100] (K=265), dst = g_mlp1
// mode 1: A = g_mlp1 (K=256), dst = g_mlp2
__global__ void __launch_bounds__(256) mlp_layer(
    const float* __restrict__ action, const float* __restrict__ time_idx,
    const float* __restrict__ W, const float* __restrict__ bias,
    int Ktot, int mode)
{
    __shared__ float As[64][17];
    __shared__ float Bs[16][64];

    int c = blockIdx.z;
    int row0 = blockIdx.x * 64;
    int col0 = blockIdx.y * 64;
    int tid = threadIdx.x;
    int tx = tid & 15;
    int ty = tid >> 4;

    float acc[4][4];
#pragma unroll
    for (int i = 0; i < 4; i++)
#pragma unroll
        for (int j = 0; j < 4; j++) acc[i][j] = 0.0f;

    const float* Wc = W + (size_t)c * Ktot * 256;
    const float* Asrc = g_mlp1 + (size_t)c * BATCH * HIDDIM;
    int KP = (Ktot + 15) & ~15;

    for (int k0 = 0; k0 < KP; k0 += 16) {
        for (int i = tid; i < 1024; i += 256) {
            int r = i >> 4, k = i & 15;
            int gb = row0 + r;
            int d = k0 + k;
            float v = 0.0f;
            if (mode == 0) {
                if (d < 256)       v = g_h[0][gb * HDIM + d];
                else if (d < 264)  v = action[gb * ADIM + (d - 256)];
                else if (d == 264) v = time_idx[gb] * 0.01f;
            } else {
                if (d < Ktot)      v = Asrc[gb * HIDDIM + d];
            }
            As[r][k] = v;
        }
        for (int i = tid; i < 1024; i += 256) {
            int kk = i >> 6, cc = i & 63;
            int d = k0 + kk;
            Bs[kk][cc] = (d < Ktot) ? Wc[(size_t)d * 256 + col0 + cc] : 0.0f;
        }
        __syncthreads();
#pragma unroll
        for (int k = 0; k < 16; k++) {
            float a[4], b[4];
#pragma unroll
            for (int i = 0; i < 4; i++) a[i] = As[ty * 4 + i][k];
#pragma unroll
            for (int j = 0; j < 4; j++) b[j] = Bs[k][tx * 4 + j];
#pragma unroll
            for (int i = 0; i < 4; i++)
#pragma unroll
                for (int j = 0; j < 4; j++) acc[i][j] += a[i] * b[j];
        }
        __syncthreads();
    }

    float* dst = (mode == 0) ? g_mlp1 : g_mlp2;
#pragma unroll
    for (int i = 0; i < 4; i++) {
        int gb = row0 + ty * 4 + i;
#pragma unroll
        for (int j = 0; j < 4; j++) {
            int col = col0 + tx * 4 + j;
            float v = acc[i][j] + bias[c * 256 + col];
            dst[((size_t)c * BATCH + gb) * HIDDIM + col] = fmaxf(v, 0.0f);
        }
    }
}

// ---------------- final projection: out[b][c] = g_mlp2[c][b][:] . W3[c][:] + b3[c] ----------------
__global__ void mlp_out(const float* __restrict__ W3, const float* __restrict__ b3,
                        float* __restrict__ out)
{
    int gw   = (blockIdx.x * blockDim.x + threadIdx.x) >> 5;
    int lane = threadIdx.x & 31;
    if (gw >= 2 * BATCH) return;
    int c = gw >> 10;
    int b = gw & 1023;
    const float* v = g_mlp2 + ((size_t)c * BATCH + b) * HIDDIM;
    const float* w = W3 + (size_t)c * HIDDIM;   // W3 is [C][256][1]
    float s = 0.0f;
    for (int i = lane; i < HIDDIM; i += 32) s += v[i] * w[i];
#pragma unroll
    for (int o = 16; o; o >>= 1) s += __shfl_xor_sync(0xffffffffu, s, o);
    if (lane == 0) out[b * 2 + c] = s + b3[c];
}

// ---------------- launch ----------------
extern "C" void kernel_launch(void* const* d_in, const int* in_sizes, int n_in,
                              void* d_out, int out_size)
{
    const float* particles = (const float*)d_in[0];
    const float* weights   = (const float*)d_in[1];
    const float* action    = (const float*)d_in[2];
    const float* time_idx  = (const float*)d_in[3];
    const float* Wi        = (const float*)d_in[4];
    const float* bi        = (const float*)d_in[5];
    const float* Wh        = (const float*)d_in[6];
    const float* bhn       = (const float*)d_in[7];
    const float* W1        = (const float*)d_in[8];
    const float* b1        = (const float*)d_in[9];
    const float* W2        = (const float*)d_in[10];
    const float* b2        = (const float*)d_in[11];
    const float* W3        = (const float*)d_in[12];
    const float* b3        = (const float*)d_in[13];
    float* out = (float*)d_out;

    prep_weights<<<(KPAD * NPACK + 255) / 256, 256>>>(Wi, Wh);
    zero_h<<<(BATCH * HDIM + 255) / 256, 256>>>();

    for (int t = 0; t < TSTEPS; ++t) {
        gru_step<<<dim3(BATCH / BM, NPACK / BN), 256>>>(particles, weights, bi, bhn, t, t & 1);
    }

    // final h is in g_h[0] after an even number of steps
    mlp_layer<<<dim3(BATCH / 64, HIDDIM / 64, 2), 256>>>(action, time_idx, W1, b1, 265, 0);
    mlp_layer<<<dim3(BATCH / 64, HIDDIM / 64, 2), 256>>>(action, time_idx, W2, b2, 256, 1);
    mlp_out<<<(2 * BATCH * 32 + 255) / 256, 256>>>(W3, b3, out);
}

// round 2
// speedup vs baseline: 4.5121x; 4.5121x over previous
#include <cuda_runtime.h>
#include <cuda_fp16.h>
#include <mma.h>

using namespace nvcuda;

// ---------------- problem constants ----------------
#define BATCH 1024
#define TSTEPS 256
#define DPART 64
#define ADIM 8
#define HDIM 256
#define HIDDIM 256
#define KH 256           // h part of K
#define KTOT 321         // h(256) + particles(64) + weight(1)
#define KPAD 336         // padded to multiple of 16
#define NPACK 1024       // 256 hidden units * 4 packed cols (r, z, nf, hpn)

// cluster decomposition
#define CSIZE 8          // CTAs per cluster (each owns 128 packed cols = 32 hidden units)
#define NCLUST 16        // clusters (each owns 64 batch rows)
#define MROWS 64         // batch rows per cluster
#define NCOLS 128        // packed cols per CTA

// SMEM strides (in elements)
#define AS_LD 344        // halves  (336 + 8 pad)
#define WS_LD 136        // halves  (128 + 8 pad)
#define CS_LD 132        // floats  (128 + 4 pad)

#define SMEM_BYTES (MROWS * AS_LD * 2 + KPAD * WS_LD * 2 + MROWS * CS_LD * 4)

// ---------------- device scratch ----------------
__device__ __half g_Wph[KPAD * NPACK];         // packed fp16 weights
__device__ __half g_hx[2][BATCH * HDIM];       // ping-pong GRU state (fp16)
__device__ float  g_mlp1[2 * BATCH * HIDDIM];
__device__ float  g_mlp2[2 * BATCH * HIDDIM];

// ---------------- weight packing ----------------
// col layout: hb in [0,8); within a 128-col block: [r(32) | z(32) | nf(32) | hpn(32)]
// rows: k<256 -> Wh[k][gatecol]; 256<=k<321 -> Wi[k-256][gatecol]; hpn panel: Wh_n only.
__global__ void prep_weights(const float* __restrict__ Wi, const float* __restrict__ Wh) {
    int idx = blockIdx.x * blockDim.x + threadIdx.x;
    if (idx >= KPAD * NPACK) return;
    int k = idx / NPACK;
    int col = idx % NPACK;
    int hb = col >> 7;
    int rem = col & 127;
    int panel = rem >> 5;
    int u = rem & 31;
    int j = hb * 32 + u;                 // hidden unit index
    float w = 0.0f;
    if (panel < 3) {
        int g = j + panel * 256;
        if (k < KH)            w = Wh[k * 768 + g];
        else if (k < KTOT)     w = Wi[(k - KH) * 768 + g];
    } else {                             // hpn panel: h @ Wh_n only
        if (k < KH)            w = Wh[k * 768 + (j + 512)];
    }
    g_Wph[idx] = __float2half(w);
}

// ---------------- persistent GRU kernel ----------------
__global__ void __cluster_dims__(CSIZE, 1, 1) __launch_bounds__(256, 1)
gru_persistent(const float* __restrict__ particles,   // [B, T, DP]
               const float* __restrict__ pweights,    // [B, T]
               const float* __restrict__ bi,          // [768]
               const float* __restrict__ bhn)         // [256]
{
    extern __shared__ char smem_raw[];
    __half* As = (__half*)smem_raw;                              // [MROWS][AS_LD]
    __half* Ws = (__half*)(smem_raw + MROWS * AS_LD * 2);        // [KPAD][WS_LD]
    float*  Cs = (float*)(smem_raw + MROWS * AS_LD * 2 + KPAD * WS_LD * 2); // [MROWS][CS_LD]

    const int tid  = threadIdx.x;
    const int rnk  = blockIdx.x & (CSIZE - 1);   // cluster rank -> col slice
    const int g    = blockIdx.x >> 3;            // cluster id   -> batch slice
    const int row0 = g * MROWS;
    const int col0 = rnk * NCOLS;

    const int warp = tid >> 5;
    const int wr   = warp & 3;     // rows wr*16
    const int wc   = warp >> 2;    // cols wc*64

    // ---- per-thread epilogue constants (u = tid&31 fixed across epilogue iters) ----
    const int u_ep = tid & 31;
    const int j_ep = rnk * 32 + u_ep;
    const float bir  = bi[j_ep];
    const float biz  = bi[256 + j_ep];
    const float bin  = bi[512 + j_ep];
    const float bhnj = bhn[j_ep];

    // ---- load weight slice into SMEM (once) ----
    {
        const uint4* src = (const uint4*)(g_Wph);
        for (int i = tid; i < KPAD * (NCOLS / 8); i += 256) {
            int r = i / (NCOLS / 8);
            int q = i % (NCOLS / 8);
            ((uint4*)(Ws + r * WS_LD))[q] =
                ((const uint4*)(g_Wph + (size_t)r * NPACK + col0))[q];
        }
    }
    // ---- zero pad cols 321..335 of As (persistent across steps) ----
    for (int i = tid; i < MROWS * 16; i += 256) {
        int r = i >> 4, c = 320 + (i & 15);
        As[r * AS_LD + c] = __float2half(0.0f);
    }
    // ---- zero own slice of h buffer 0 ----
    for (int i = tid; i < MROWS * 32; i += 256) {
        int r = i >> 5, u = i & 31;
        g_hx[0][(row0 + r) * HDIM + rnk * 32 + u] = __float2half(0.0f);
    }
    __syncthreads();
    asm volatile("barrier.cluster.arrive.aligned;" ::: "memory");
    asm volatile("barrier.cluster.wait.aligned;" ::: "memory");

    for (int t = 0; t < TSTEPS; ++t) {
        const int p = t & 1;
        const __half* __restrict__ hin = g_hx[p];

        // ---- build A tile: [h(256) | particles_t(64) | weight_t(1) | pad] ----
        // h columns (fp16, coalesced uint4 = 8 halves)
        for (int i = tid; i < MROWS * 32; i += 256) {
            int r = i >> 5, q = i & 31;
            ((uint4*)(As + r * AS_LD))[q] =
                ((const uint4*)(hin + (row0 + r) * HDIM))[q];
        }
        // particle columns (fp32 -> fp16)
        for (int i = tid; i < MROWS * 16; i += 256) {
            int r = i >> 4, q = i & 15;
            float4 v = ((const float4*)(particles + ((size_t)(row0 + r) * TSTEPS + t) * DPART))[q];
            __half2 h0 = __floats2half2_rn(v.x, v.y);
            __half2 h1 = __floats2half2_rn(v.z, v.w);
            __half2* dst = (__half2*)(As + r * AS_LD + 256 + q * 4);
            dst[0] = h0; dst[1] = h1;
        }
        // weight channel col 320
        if (tid < MROWS) {
            As[tid * AS_LD + 320] = __float2half(pweights[(size_t)(row0 + tid) * TSTEPS + t]);
        }
        __syncthreads();

        // ---- GEMM: C[64,128] = A[64,336] @ Ws[336,128] (fp16 in, fp32 acc) ----
        wmma::fragment<wmma::accumulator, 16, 16, 16, float> acc[4];
#pragma unroll
        for (int i = 0; i < 4; i++) wmma::fill_fragment(acc[i], 0.0f);

#pragma unroll
        for (int kk = 0; kk < KPAD; kk += 16) {
            wmma::fragment<wmma::matrix_a, 16, 16, 16, __half, wmma::row_major> af;
            wmma::load_matrix_sync(af, As + (wr * 16) * AS_LD + kk, AS_LD);
#pragma unroll
            for (int ct = 0; ct < 4; ct++) {
                wmma::fragment<wmma::matrix_b, 16, 16, 16, __half, wmma::row_major> bf;
                wmma::load_matrix_sync(bf, Ws + kk * WS_LD + wc * 64 + ct * 16, WS_LD);
                wmma::mma_sync(acc[ct], af, bf, acc[ct]);
            }
        }
#pragma unroll
        for (int ct = 0; ct < 4; ct++)
            wmma::store_matrix_sync(Cs + (wr * 16) * CS_LD + wc * 64 + ct * 16,
                                    acc[ct], CS_LD, wmma::mem_row_major);
        __syncthreads();

        // ---- fused GRU gate epilogue: 64 rows x 32 hidden units ----
        __half* __restrict__ hout = g_hx[p ^ 1];
        for (int i = tid; i < MROWS * 32; i += 256) {
            int r = i >> 5;                         // u = u_ep (fixed per thread)
            float sr  = Cs[r * CS_LD + u_ep]       + bir;
            float sz  = Cs[r * CS_LD + 32 + u_ep]  + biz;
            float snf = Cs[r * CS_LD + 64 + u_ep]  + bin;
            float hpn = Cs[r * CS_LD + 96 + u_ep];
            float rg = __fdividef(1.0f, 1.0f + __expf(-sr));
            float zg = __fdividef(1.0f, 1.0f + __expf(-sz));
            float arg = (snf - hpn) + rg * (hpn + bhnj);
            arg = fminf(fmaxf(arg, -15.0f), 15.0f);
            float e2 = __expf(-2.0f * arg);
            float ng = __fdividef(1.0f - e2, 1.0f + e2);   // tanh
            float ho = __half2float(As[r * AS_LD + j_ep]);
            float hn = (1.0f - zg) * ng + zg * ho;
            hout[(size_t)(row0 + r) * HDIM + j_ep] = __float2half(hn);
        }

        // ---- publish h to cluster peers (release) / consume (acquire) ----
        asm volatile("barrier.cluster.arrive.aligned;" ::: "memory");
        asm volatile("barrier.cluster.wait.aligned;" ::: "memory");
    }
}

// ---------------- MLP layers (fp32 SIMT tiled GEMM, 64x64x16, 4x4 microtile) ----------------
__global__ void __launch_bounds__(256) mlp_layer(
    const float* __restrict__ action, const float* __restrict__ time_idx,
    const float* __restrict__ W, const float* __restrict__ bias,
    int Ktot, int mode)
{
    __shared__ float As[64][17];
    __shared__ float Bs[16][64];

    int c = blockIdx.z;
    int row0 = blockIdx.x * 64;
    int col0 = blockIdx.y * 64;
    int tid = threadIdx.x;
    int tx = tid & 15;
    int ty = tid >> 4;

    float acc[4][4];
#pragma unroll
    for (int i = 0; i < 4; i++)
#pragma unroll
        for (int j = 0; j < 4; j++) acc[i][j] = 0.0f;

    const float* Wc = W + (size_t)c * Ktot * 256;
    const float* Asrc = g_mlp1 + (size_t)c * BATCH * HIDDIM;
    int KP = (Ktot + 15) & ~15;

    for (int k0 = 0; k0 < KP; k0 += 16) {
        for (int i = tid; i < 1024; i += 256) {
            int r = i >> 4, k = i & 15;
            int gb = row0 + r;
            int d = k0 + k;
            float v = 0.0f;
            if (mode == 0) {
                if (d < 256)       v = __half2float(g_hx[0][gb * HDIM + d]);
                else if (d < 264)  v = action[gb * ADIM + (d - 256)];
                else if (d == 264) v = time_idx[gb] * 0.01f;
            } else {
                if (d < Ktot)      v = Asrc[gb * HIDDIM + d];
            }
            As[r][k] = v;
        }
        for (int i = tid; i < 1024; i += 256) {
            int kk = i >> 6, cc = i & 63;
            int d = k0 + kk;
            Bs[kk][cc] = (d < Ktot) ? Wc[(size_t)d * 256 + col0 + cc] : 0.0f;
        }
        __syncthreads();
#pragma unroll
        for (int k = 0; k < 16; k++) {
            float a[4], b[4];
#pragma unroll
            for (int i = 0; i < 4; i++) a[i] = As[ty * 4 + i][k];
#pragma unroll
            for (int j = 0; j < 4; j++) b[j] = Bs[k][tx * 4 + j];
#pragma unroll
            for (int i = 0; i < 4; i++)
#pragma unroll
                for (int j = 0; j < 4; j++) acc[i][j] += a[i] * b[j];
        }
        __syncthreads();
    }

    float* dst = (mode == 0) ? g_mlp1 : g_mlp2;
#pragma unroll
    for (int i = 0; i < 4; i++) {
        int gb = row0 + ty * 4 + i;
#pragma unroll
        for (int j = 0; j < 4; j++) {
            int col = col0 + tx * 4 + j;
            float v = acc[i][j] + bias[c * 256 + col];
            dst[((size_t)c * BATCH + gb) * HIDDIM + col] = fmaxf(v, 0.0f);
        }
    }
}

// ---------------- final projection ----------------
__global__ void mlp_out(const float* __restrict__ W3, const float* __restrict__ b3,
                        float* __restrict__ out)
{
    int gw   = (blockIdx.x * blockDim.x + threadIdx.x) >> 5;
    int lane = threadIdx.x & 31;
    if (gw >= 2 * BATCH) return;
    int c = gw >> 10;
    int b = gw & 1023;
    const float* v = g_mlp2 + ((size_t)c * BATCH + b) * HIDDIM;
    const float* w = W3 + (size_t)c * HIDDIM;
    float s = 0.0f;
    for (int i = lane; i < HIDDIM; i += 32) s += v[i] * w[i];
#pragma unroll
    for (int o = 16; o; o >>= 1) s += __shfl_xor_sync(0xffffffffu, s, o);
    if (lane == 0) out[b * 2 + c] = s + b3[c];
}

// ---------------- launch ----------------
extern "C" void kernel_launch(void* const* d_in, const int* in_sizes, int n_in,
                              void* d_out, int out_size)
{
    const float* particles = (const float*)d_in[0];
    const float* weights   = (const float*)d_in[1];
    const float* action    = (const float*)d_in[2];
    const float* time_idx  = (const float*)d_in[3];
    const float* Wi        = (const float*)d_in[4];
    const float* bi        = (const float*)d_in[5];
    const float* Wh        = (const float*)d_in[6];
    const float* bhn       = (const float*)d_in[7];
    const float* W1        = (const float*)d_in[8];
    const float* b1        = (const float*)d_in[9];
    const float* W2        = (const float*)d_in[10];
    const float* b2        = (const float*)d_in[11];
    const float* W3        = (const float*)d_in[12];
    const float* b3        = (const float*)d_in[13];
    float* out = (float*)d_out;

    cudaFuncSetAttribute(gru_persistent,
                         cudaFuncAttributeMaxDynamicSharedMemorySize, SMEM_BYTES);

    prep_weights<<<(KPAD * NPACK + 255) / 256, 256>>>(Wi, Wh);

    gru_persistent<<<NCLUST * CSIZE, 256, SMEM_BYTES>>>(particles, weights, bi, bhn);

    mlp_layer<<<dim3(BATCH / 64, HIDDIM / 64, 2), 256>>>(action, time_idx, W1, b1, 265, 0);
    mlp_layer<<<dim3(BATCH / 64, HIDDIM / 64, 2), 256>>>(action, time_idx, W2, b2, 256, 1);
    mlp_out<<<(2 * BATCH * 32 + 255) / 256, 256>>>(W3, b3, out);
}